// round 10
// baseline (speedup 1.0000x reference)
#include <cuda_runtime.h>
#include <cstdint>

// Problem constants
#define S_    8
#define U_    8
#define K_    12
#define NEG_  17
#define ZD    64
#define CD    256
#define T_    1140
#define LEN   1128
#define SU    64
#define TOTPOS 72192

#define NCTA 144
#define TILES_PER_CTA 24        // 144*24 = 3456 = 6 kpairs * 9 ltiles * 64 su

__device__ double g_loss[K_];
__device__ double g_acc[K_];

__global__ void zero_accum() {
    int i = threadIdx.x;
    if (i < K_) { g_loss[i] = 0.0; g_acc[i] = 0.0; }
}

__device__ __forceinline__ void bar0() {
    asm volatile("bar.sync 0;" ::: "memory");
}

// ---------------- smem layout (float offsets) ----------------
#define ASB 132                       // padded stride
#define OFF_AS 0                      // As[32][132]
#define OFF_BS (32 * ASB)             // Bs[32][132]
#define OFF_WC (64 * ASB)             // wc double buffer
#define WC_BUF (128 * ASB)
#define OFF_SL (OFF_WC + 2 * WC_BUF)  // sLoss[12]
#define OFF_SA (OFF_SL + 12)          // sAcc[12]
#define SMEM_FLOATS (OFF_SA + 12 + 4)
#define SMEM_BYTES (SMEM_FLOATS * 4)  // ~169 KB

// ================= fused producer/consumer (full-CTA barriers only) =================
// Warps 0-7 (256 thr): FFMA GEMM tile [128 l x 128 n] (n = 2 k-slices) -> wc[i&1].
// Warps 8-15: CPC loss for tile i-1 from wc[(i-1)&1].
// Both sides execute exactly 17 bar.sync 0 per outer iteration; work between
// barriers overlaps FMA-pipe (producer) with L2 gather (consumer).
__global__ __launch_bounds__(512, 1) void fused_ws2(
    const float* __restrict__ C,
    const float* __restrict__ W,
    const float* __restrict__ Bias,
    const float* __restrict__ z,
    const int* __restrict__ batch_index,
    const int* __restrict__ seq_index)
{
    extern __shared__ float smf[];
    float* As    = smf + OFF_AS;
    float* Bs    = smf + OFF_BS;
    float* sLoss = smf + OFF_SL;
    float* sAcc  = smf + OFF_SA;

    const int tid = threadIdx.x;
    if (tid < 12) { sLoss[tid] = 0.0f; sAcc[tid] = 0.0f; }
    bar0();                                    // prologue (1 per thread)

    if (tid < 256) {
        // ======================= PRODUCER =======================
        const int ty = tid >> 4;
        const int tx = tid & 15;

        for (int i = 0; i <= TILES_PER_CTA; i++) {
            if (i < TILES_PER_CTA) {
                const int t  = blockIdx.x * TILES_PER_CTA + i;
                const int kp = t % 6;
                const int rs = t / 6;
                const int lt = rs % 9;
                const int su = rs / 9;
                const int k0 = kp * 2;
                const int l0 = lt * 128;
                float* wc = smf + OFF_WC + (i & 1) * WC_BUF;

                float acc[8][8];
#pragma unroll
                for (int a = 0; a < 8; a++)
#pragma unroll
                    for (int b = 0; b < 8; b++) acc[a][b] = 0.0f;

                for (int r2 = 0; r2 < 8; r2++) {
                    const int ktb = r2 * 32;
                    // load A chunk: 128 rows x 32 cols = 1024 float4, 4/thread
#pragma unroll
                    for (int r = 0; r < 4; r++) {
                        int f = r * 256 + tid;
                        int row = f >> 3, c4 = f & 7;
                        int rr = l0 + row; if (rr > T_ - 1) rr = T_ - 1;
                        const float4 v = *(const float4*)(C + ((size_t)su * T_ + rr) * CD + ktb + c4 * 4);
                        As[(c4 * 4 + 0) * ASB + row] = v.x;
                        As[(c4 * 4 + 1) * ASB + row] = v.y;
                        As[(c4 * 4 + 2) * ASB + row] = v.z;
                        As[(c4 * 4 + 3) * ASB + row] = v.w;
                    }
                    // load B chunk: 128 n x 32 cols
#pragma unroll
                    for (int r = 0; r < 4; r++) {
                        int f = r * 256 + tid;
                        int n = f >> 3, c4 = f & 7;
                        const float* brow = W + ((size_t)(k0 + (n >> 6)) * ZD + (n & 63)) * CD;
                        const float4 v = *(const float4*)(brow + ktb + c4 * 4);
                        Bs[(c4 * 4 + 0) * ASB + n] = v.x;
                        Bs[(c4 * 4 + 1) * ASB + n] = v.y;
                        Bs[(c4 * 4 + 2) * ASB + n] = v.z;
                        Bs[(c4 * 4 + 3) * ASB + n] = v.w;
                    }
                    bar0();
#pragma unroll 16
                    for (int kk = 0; kk < 32; kk++) {
                        float4 a0 = *(const float4*)&As[kk * ASB + ty * 8];
                        float4 a1 = *(const float4*)&As[kk * ASB + ty * 8 + 4];
                        float4 b0 = *(const float4*)&Bs[kk * ASB + tx * 8];
                        float4 b1 = *(const float4*)&Bs[kk * ASB + tx * 8 + 4];
                        float a[8] = {a0.x, a0.y, a0.z, a0.w, a1.x, a1.y, a1.z, a1.w};
                        float b[8] = {b0.x, b0.y, b0.z, b0.w, b1.x, b1.y, b1.z, b1.w};
#pragma unroll
                        for (int x = 0; x < 8; x++)
#pragma unroll
                            for (int y = 0; y < 8; y++) acc[x][y] += a[x] * b[y];
                    }
                    bar0();
                }

                // bias + write wc[i&1]
                float bias[8];
#pragma unroll
                for (int j = 0; j < 8; j++) {
                    int n = tx * 8 + j;
                    bias[j] = __ldg(Bias + (k0 + (n >> 6)) * ZD + (n & 63));
                }
#pragma unroll
                for (int x = 0; x < 8; x++) {
                    int row = ty * 8 + x;
#pragma unroll
                    for (int j = 0; j < 8; j++)
                        wc[row * ASB + tx * 8 + j] = acc[x][j] + bias[j];
                }
                bar0();                       // tile barrier (#17)
            } else {
                for (int b = 0; b < 16; b++) bar0();
                bar0();
            }
        }
    } else {
        // ======================= CONSUMER =======================
        const int ctid = tid - 256;
        const int lane = ctid & 31;
        const int g8   = ctid >> 3;
        const int lg   = ctid & 7;
        const unsigned gmask = 0xFFu << ((lane >> 3) * 8);

        for (int i = 0; i <= TILES_PER_CTA; i++) {
            if (i >= 1) {
                const int t  = blockIdx.x * TILES_PER_CTA + (i - 1);
                const int kp = t % 6;
                const int rs = t / 6;
                const int lt = rs % 9;
                const int su = rs / 9;
                const int k0 = kp * 2;
                const int l0 = lt * 128;
                const int s = su >> 3, u = su & 7;
                const float* wc = smf + OFF_WC + ((i - 1) & 1) * WC_BUF;

                float lts0 = 0.f, lts1 = 0.f, oks0 = 0.f, oks1 = 0.f;

#pragma unroll 1
                for (int j = 0; j < 8; j++) {
                    const int pair = g8 * 8 + j;
                    const int lrow = pair >> 1;
                    const int kh   = j & 1;
                    const int l    = l0 + lrow;
                    const bool act = (l < LEN);
                    const int k = k0 + kh;
                    const int kshift = k + 1;

                    float4 wa, wb;
                    float pos = 0.f, m = 0.f, ssum = 1.f, ok = 1.f;
                    int bis[NEG_], sis[NEG_];

                    if (act) {
                        const float* wrow = wc + lrow * ASB + kh * 64;
                        wa = *(const float4*)(wrow + 4 * lg);
                        wb = *(const float4*)(wrow + 32 + 4 * lg);

                        const float* zp = z + ((size_t)(su * T_ + l + kshift)) * ZD;
                        float4 za = *(const float4*)(zp + 4 * lg);
                        float4 zb = *(const float4*)(zp + 32 + 4 * lg);
                        float v = wa.x * za.x + wa.y * za.y + wa.z * za.z + wa.w * za.w
                                + wb.x * zb.x + wb.y * zb.y + wb.z * zb.z + wb.w * zb.w;
                        v += __shfl_xor_sync(gmask, v, 1);
                        v += __shfl_xor_sync(gmask, v, 2);
                        v += __shfl_xor_sync(gmask, v, 4);
                        pos = v * 0.125f;

                        const int* bip = batch_index + (k * U_ + u) * NEG_;
                        const int* sip = seq_index + ((size_t)((k * S_ + s) * U_ + u) * NEG_) * LEN + l;
#pragma unroll
                        for (int n = 0; n < NEG_; n++) {
                            bis[n] = __ldg(bip + n);
                            sis[n] = __ldg(sip + (size_t)n * LEN);
                        }

                        m = pos;
#pragma unroll
                        for (int n = 0; n < 8; n++) {
                            const float* zr = z + ((size_t)((s * 8 + bis[n]) * T_ + sis[n] + kshift)) * ZD;
                            float4 na = *(const float4*)(zr + 4 * lg);
                            float4 nb = *(const float4*)(zr + 32 + 4 * lg);
                            float d = wa.x * na.x + wa.y * na.y + wa.z * na.z + wa.w * na.w
                                    + wb.x * nb.x + wb.y * nb.y + wb.z * nb.z + wb.w * nb.w;
                            d += __shfl_xor_sync(gmask, d, 1);
                            d += __shfl_xor_sync(gmask, d, 2);
                            d += __shfl_xor_sync(gmask, d, 4);
                            d *= 0.125f;
                            if (d > pos) ok = 0.0f;
                            if (d > m) { ssum = ssum * __expf(m - d) + 1.0f; m = d; }
                            else       { ssum += __expf(d - m); }
                        }
                    }
                    bar0();
                    if (act) {
#pragma unroll
                        for (int n = 8; n < NEG_; n++) {
                            const float* zr = z + ((size_t)((s * 8 + bis[n]) * T_ + sis[n] + kshift)) * ZD;
                            float4 na = *(const float4*)(zr + 4 * lg);
                            float4 nb = *(const float4*)(zr + 32 + 4 * lg);
                            float d = wa.x * na.x + wa.y * na.y + wa.z * na.z + wa.w * na.w
                                    + wb.x * nb.x + wb.y * nb.y + wb.z * nb.z + wb.w * nb.w;
                            d += __shfl_xor_sync(gmask, d, 1);
                            d += __shfl_xor_sync(gmask, d, 2);
                            d += __shfl_xor_sync(gmask, d, 4);
                            d *= 0.125f;
                            if (d > pos) ok = 0.0f;
                            if (d > m) { ssum = ssum * __expf(m - d) + 1.0f; m = d; }
                            else       { ssum += __expf(d - m); }
                        }
                        float res = m + __logf(ssum) - pos;
                        if (kh) { lts1 += res; oks1 += ok; }
                        else    { lts0 += res; oks0 += ok; }
                    }
                    bar0();
                }

                // warp reduce (values uniform within 8-lane groups) + smem accumulate
                lts0 += __shfl_xor_sync(0xffffffffu, lts0, 8);
                lts0 += __shfl_xor_sync(0xffffffffu, lts0, 16);
                lts1 += __shfl_xor_sync(0xffffffffu, lts1, 8);
                lts1 += __shfl_xor_sync(0xffffffffu, lts1, 16);
                oks0 += __shfl_xor_sync(0xffffffffu, oks0, 8);
                oks0 += __shfl_xor_sync(0xffffffffu, oks0, 16);
                oks1 += __shfl_xor_sync(0xffffffffu, oks1, 8);
                oks1 += __shfl_xor_sync(0xffffffffu, oks1, 16);
                if (lane == 0) {
                    atomicAdd(&sLoss[k0],     lts0);
                    atomicAdd(&sLoss[k0 + 1], lts1);
                    atomicAdd(&sAcc[k0],      oks0);
                    atomicAdd(&sAcc[k0 + 1],  oks1);
                }
                bar0();                       // tile barrier (#17)
            } else {
                for (int b = 0; b < 16; b++) bar0();
                bar0();
            }
        }
    }

    bar0();                                    // epilogue (1 per thread)
    if (tid < 12) {
        atomicAdd(&g_loss[tid], (double)sLoss[tid]);
        atomicAdd(&g_acc[tid],  (double)sAcc[tid]);
    }
}

// ================= finalize =================
__global__ void finalize(float* __restrict__ out, int out_size) {
    if (threadIdx.x == 0) {
        double tot = 0.0;
#pragma unroll
        for (int kk = 0; kk < K_; kk++) tot += g_loss[kk];
        if (out_size > 0) out[0] = (float)(tot / ((double)K_ * (double)TOTPOS));
#pragma unroll
        for (int kk = 0; kk < K_; kk++)
            if (1 + kk < out_size) out[1 + kk] = (float)(g_acc[kk] / (double)TOTPOS);
    }
}

// ---------------- launch ----------------
extern "C" void kernel_launch(void* const* d_in, const int* in_sizes, int n_in,
                              void* d_out, int out_size) {
    const float* z  = (const float*)d_in[0];
    const float* c  = (const float*)d_in[1];
    const float* W  = (const float*)d_in[2];
    const float* b  = (const float*)d_in[3];
    const int* bidx = (const int*)d_in[4];
    const int* sidx = (const int*)d_in[5];

    cudaFuncSetAttribute(fused_ws2, cudaFuncAttributeMaxDynamicSharedMemorySize, SMEM_BYTES);

    zero_accum<<<1, 32>>>();

    fused_ws2<<<NCTA, 512, SMEM_BYTES>>>(c, W, b, z, bidx, sidx);

    finalize<<<1, 32>>>((float*)d_out, out_size);
}